// round 12
// baseline (speedup 1.0000x reference)
#include <cuda_runtime.h>
#include <cuda_bf16.h>
#include <math.h>
#include <stdint.h>

// ---------------- problem constants ----------------
#define B_    4
#define IMG_H 1024
#define IMG_W 1536

#define H1 512
#define W1 768
#define H2 256
#define W2 384
#define H3 128
#define W3 192
#define HF 64
#define WF 96

#define C1 32
#define C2 64
#define C3 128
#define C4 128

#define OUTC  64
#define DBINS 16
#define NYV 256
#define NXV 256
#define SV  (NYV*NXV)

// ---------------- scratch (static device globals; no allocation) ----------------
__device__ float g_im[(size_t)B_ * IMG_H * IMG_W * 4];   // NHWC padded C=4
__device__ float g_x1[(size_t)B_ * H1 * W1 * C1];
__device__ float g_x2[(size_t)B_ * H2 * W2 * C2];
__device__ float g_x3[(size_t)B_ * H3 * W3 * C3];
__device__ float g_x4[(size_t)B_ * HF * WF * C4];
__device__ float g_fh[(size_t)B_ * HF * WF * C4];
__device__ float g_canvas[(size_t)B_ * SV * OUTC];
__device__ float g_wacc[B_ * SV];

__device__ float g_wt1[36 * 32];
// gemm-layer B images: [chunk][oc][32] fp32
__device__ float g_wb2[9  * 64  * 32];
__device__ float g_wb3[18 * 128 * 32];
__device__ float g_wb4[36 * 128 * 32];
__device__ float g_wb5[36 * 128 * 32];

// ---------------- zero canvas ----------------
__global__ void zero_kernel() {
    int n1 = B_ * SV * OUTC;
    int n2 = B_ * SV;
    for (int i = blockIdx.x * blockDim.x + threadIdx.x; i < n1; i += gridDim.x * blockDim.x)
        g_canvas[i] = 0.f;
    for (int i = blockIdx.x * blockDim.x + threadIdx.x; i < n2; i += gridDim.x * blockDim.x)
        g_wacc[i] = 0.f;
}

// ---------------- conv1 weight transpose ----------------
__global__ void wprep1(const float* __restrict__ w) {
    int i = blockIdx.x * blockDim.x + threadIdx.x;
    if (i >= 36 * 32) return;
    int oc = i % 32;
    int k  = i / 32;
    int tap = k / 4;
    int ic  = k % 4;
    g_wt1[i] = (ic < 3) ? w[(oc * 3 + ic) * 9 + tap] : 0.f;
}

// ---------------- gemm-layer weight prep: [chunk][oc][32] fp32 ----------------
__global__ void wprep_mma(const float* __restrict__ w, float* __restrict__ out,
                          int CIN, int OC, int NCH) {
    int i = blockIdx.x * blockDim.x + threadIdx.x;
    if (i >= NCH * OC * 32) return;
    int j  = i & 31;
    int oc = (i >> 5) % OC;
    int ch = i / (OC * 32);
    int kg = ch * 32 + j;
    int tap = kg / CIN;
    int ic  = kg % CIN;
    out[i] = w[(oc * CIN + ic) * 9 + tap];
}

// ---------------- images NCHW -> NHWC padded C=4 ----------------
__global__ void im2nhwc(const float* __restrict__ im) {
    int i = blockIdx.x * blockDim.x + threadIdx.x;
    const int HW = IMG_H * IMG_W;
    if (i >= B_ * HW) return;
    int b = i / HW;
    int p = i % HW;
    const float* base = im + (size_t)b * 3 * HW + p;
    float4 v;
    v.x = base[0];
    v.y = base[HW];
    v.z = base[2 * HW];
    v.w = 0.f;
    *(float4*)&g_im[(size_t)i * 4] = v;
}

// ---------------- conv1: direct fp32 ----------------
__global__ __launch_bounds__(256) void conv1_kernel(const float* __restrict__ sc,
                                                    const float* __restrict__ bi) {
    __shared__ float ws[36 * 32];
    __shared__ float ssc[32], sbi[32];
    int tid = threadIdx.x;
    for (int i = tid; i < 36 * 32; i += 256) ws[i] = g_wt1[i];
    if (tid < 32) { ssc[tid] = sc[tid]; sbi[tid] = bi[tid]; }
    __syncthreads();

    int p = blockIdx.x * 256 + tid;
    const int HW = H1 * W1;
    int b  = p / HW;
    int r  = p % HW;
    int oh = r / W1;
    int ow = r % W1;
    int ihb = oh * 2 - 1;
    int iwb = ow * 2 - 1;

    float4 patch[9];
    #pragma unroll
    for (int t = 0; t < 9; t++) {
        int kh = t / 3, kw = t % 3;
        int ih = ihb + kh, iw = iwb + kw;
        float4 v = make_float4(0.f, 0.f, 0.f, 0.f);
        if ((unsigned)ih < (unsigned)IMG_H && (unsigned)iw < (unsigned)IMG_W)
            v = *(const float4*)&g_im[(((size_t)b * IMG_H + ih) * IMG_W + iw) * 4];
        patch[t] = v;
    }

    float4 acc[8];
    #pragma unroll
    for (int q = 0; q < 8; q++) acc[q] = make_float4(0.f, 0.f, 0.f, 0.f);

    #pragma unroll
    for (int t = 0; t < 9; t++) {
        #pragma unroll
        for (int ic = 0; ic < 4; ic++) {
            float a = (ic == 0) ? patch[t].x : (ic == 1) ? patch[t].y :
                      (ic == 2) ? patch[t].z : patch[t].w;
            int k = t * 4 + ic;
            #pragma unroll
            for (int q = 0; q < 8; q++) {
                float4 wv = ((float4*)ws)[k * 8 + q];
                acc[q].x += a * wv.x;
                acc[q].y += a * wv.y;
                acc[q].z += a * wv.z;
                acc[q].w += a * wv.w;
            }
        }
    }

    float* outp = &g_x1[(size_t)p * C1];
    #pragma unroll
    for (int q = 0; q < 8; q++) {
        float4 v;
        v.x = fmaxf(acc[q].x * ssc[q * 4 + 0] + sbi[q * 4 + 0], 0.f);
        v.y = fmaxf(acc[q].y * ssc[q * 4 + 1] + sbi[q * 4 + 1], 0.f);
        v.z = fmaxf(acc[q].z * ssc[q * 4 + 2] + sbi[q * 4 + 2], 0.f);
        v.w = fmaxf(acc[q].w * ssc[q * 4 + 3] + sbi[q * 4 + 3], 0.f);
        *(float4*)&outp[q * 4] = v;
    }
}

// ---------------- fp32 implicit-GEMM conv v2: transposed A tile, float4 LDS ----------------
// BM=128 pix, BN=64 oc, BK=32. 256 threads, thread tile 8 pix x 4 oc.
// As[k][pix] stride 132 (2x LDS.128 per 8-pix row slice), Bs[k][oc] stride 68.
#define A_CH (32 * 132)      // floats per A chunk buffer
#define B_CH (32 * 68)       // floats per B chunk buffer
#define SMEMB ((2 * A_CH + 2 * B_CH) * 4)   // 51200 bytes

template <int CIN, int OC, int S, int H, int W, int OH, int OW>
__global__ __launch_bounds__(256)
void conv_gemm2(const float* __restrict__ in, const float* __restrict__ wb,
                const float* __restrict__ sc, const float* __restrict__ bi,
                float* __restrict__ out)
{
    constexpr int NCH = 9 * CIN / 32;

    extern __shared__ float smf[];
    float* As = smf;                 // [2][32][132]
    float* Bs = smf + 2 * A_CH;      // [2][32][68]

    const int tid = threadIdx.x;
    const int pix0 = blockIdx.x * 128;
    const int oc0  = blockIdx.y * 64;

    // A-load mapping: row = tid>>1 (0..127), seg = (tid&1)*16 channels
    const int row = tid >> 1;
    const int seg = (tid & 1) * 16;
    int p = pix0 + row;
    int b = p / (OH * OW);
    int r = p % (OH * OW);
    int oh = r / OW;
    int ow = r % OW;
    const int ihb = oh * S - 1;
    const int iwb = ow * S - 1;

    // B-load mapping: bo = tid>>2 (0..63), kq = (tid&3)*8
    const int bo = tid >> 2;
    const int kq = (tid & 3) * 8;

    // compute mapping: tn = tid&15 (oc group of 4), tm = tid>>4 (pix group of 8)
    const int tn = tid & 15;
    const int tm = tid >> 4;

    float4 acc[8];
    #pragma unroll
    for (int q = 0; q < 8; q++) acc[q] = make_float4(0.f, 0.f, 0.f, 0.f);

    float4 aR[4];
    float4 bR[2];

    auto loadg = [&](int c) {
        int kg0 = c * 32 + seg;
        int tap = kg0 / CIN;
        int ic0 = kg0 % CIN;
        int ih = ihb + tap / 3;
        int iw = iwb + tap % 3;
        bool valid = ((unsigned)ih < (unsigned)H) && ((unsigned)iw < (unsigned)W);
        if (valid) {
            const float4* src = (const float4*)(in + ((size_t)(b * H + ih) * W + iw) * CIN + ic0);
            #pragma unroll
            for (int g = 0; g < 4; g++) aR[g] = src[g];
        } else {
            #pragma unroll
            for (int g = 0; g < 4; g++) aR[g] = make_float4(0.f, 0.f, 0.f, 0.f);
        }
        const float4* bsrc = (const float4*)(wb + ((size_t)c * OC + oc0 + bo) * 32 + kq);
        bR[0] = bsrc[0];
        bR[1] = bsrc[1];
    };

    auto store_s = [&](int buf) {
        float* Ab = As + buf * A_CH;
        #pragma unroll
        for (int g = 0; g < 4; g++) {
            Ab[(seg + g * 4 + 0) * 132 + row] = aR[g].x;
            Ab[(seg + g * 4 + 1) * 132 + row] = aR[g].y;
            Ab[(seg + g * 4 + 2) * 132 + row] = aR[g].z;
            Ab[(seg + g * 4 + 3) * 132 + row] = aR[g].w;
        }
        float* Bb = Bs + buf * B_CH;
        #pragma unroll
        for (int g = 0; g < 2; g++) {
            Bb[(kq + g * 4 + 0) * 68 + bo] = (g == 0 ? bR[0].x : bR[1].x);
            Bb[(kq + g * 4 + 1) * 68 + bo] = (g == 0 ? bR[0].y : bR[1].y);
            Bb[(kq + g * 4 + 2) * 68 + bo] = (g == 0 ? bR[0].z : bR[1].z);
            Bb[(kq + g * 4 + 3) * 68 + bo] = (g == 0 ? bR[0].w : bR[1].w);
        }
    };

    loadg(0);
    store_s(0);
    __syncthreads();

    for (int c = 0; c < NCH; c++) {
        const int buf = c & 1;
        if (c + 1 < NCH) loadg(c + 1);

        const float* Ab = As + buf * A_CH + tm * 8;
        const float* Bb = Bs + buf * B_CH + tn * 4;

        #pragma unroll
        for (int k = 0; k < 32; k++) {
            float4 b4 = *(const float4*)&Bb[k * 68];
            float4 a0 = *(const float4*)&Ab[k * 132];
            float4 a1 = *(const float4*)&Ab[k * 132 + 4];
            acc[0].x += a0.x * b4.x; acc[0].y += a0.x * b4.y; acc[0].z += a0.x * b4.z; acc[0].w += a0.x * b4.w;
            acc[1].x += a0.y * b4.x; acc[1].y += a0.y * b4.y; acc[1].z += a0.y * b4.z; acc[1].w += a0.y * b4.w;
            acc[2].x += a0.z * b4.x; acc[2].y += a0.z * b4.y; acc[2].z += a0.z * b4.z; acc[2].w += a0.z * b4.w;
            acc[3].x += a0.w * b4.x; acc[3].y += a0.w * b4.y; acc[3].z += a0.w * b4.z; acc[3].w += a0.w * b4.w;
            acc[4].x += a1.x * b4.x; acc[4].y += a1.x * b4.y; acc[4].z += a1.x * b4.z; acc[4].w += a1.x * b4.w;
            acc[5].x += a1.y * b4.x; acc[5].y += a1.y * b4.y; acc[5].z += a1.y * b4.z; acc[5].w += a1.y * b4.w;
            acc[6].x += a1.z * b4.x; acc[6].y += a1.z * b4.y; acc[6].z += a1.z * b4.z; acc[6].w += a1.z * b4.w;
            acc[7].x += a1.w * b4.x; acc[7].y += a1.w * b4.y; acc[7].z += a1.w * b4.z; acc[7].w += a1.w * b4.w;
        }

        if (c + 1 < NCH) {
            store_s((c + 1) & 1);
            __syncthreads();
        }
    }
    __syncthreads();

    // ---- epilogue: stage in smem, scale+bias+relu, coalesced NHWC store ----
    float* osm = smf;                 // [128][68]
    #pragma unroll
    for (int q = 0; q < 8; q++)
        *(float4*)&osm[(tm * 8 + q) * 68 + tn * 4] = acc[q];
    __syncthreads();

    {
        const int orow = tid >> 1;
        const int oseg = (tid & 1) * 32;
        float vv[32];
        #pragma unroll
        for (int i = 0; i < 32; i++) {
            int oc = oc0 + oseg + i;
            vv[i] = fmaxf(osm[orow * 68 + oseg + i] * __ldg(&sc[oc]) + __ldg(&bi[oc]), 0.f);
        }
        float4* dst = (float4*)(out + (size_t)(pix0 + orow) * OC + oc0 + oseg);
        #pragma unroll
        for (int q = 0; q < 8; q++) dst[q] = ((float4*)vv)[q];
    }
}

// ---------------- heads + depth lift + backprojection + gaussian splat ----------------
__global__ void heads_splat(const float* __restrict__ x4, const float* __restrict__ fh,
                            const float* __restrict__ fw2, const float* __restrict__ fb2,
                            const float* __restrict__ dw,  const float* __restrict__ db,
                            const float* __restrict__ oww, const float* __restrict__ ob,
                            const float* __restrict__ camK, const float* __restrict__ Tlc,
                            const int* __restrict__ imgh, const int* __restrict__ imgw)
{
    const int pix = blockIdx.x;
    const int w   = pix % WF;
    int t = pix / WF;
    const int h = t % HF;
    const int b = t / HF;
    const int tid = threadIdx.x;

    __shared__ float sx4[C4];
    __shared__ float sfh[C4];
    __shared__ float sfeat[OUTC];
    __shared__ float sdl[DBINS];
    __shared__ float sprm[4];

    sx4[tid] = x4[(size_t)pix * C4 + tid];
    sfh[tid] = fh[(size_t)pix * C4 + tid];
    __syncthreads();

    if (tid < OUTC) {
        float a = 0.f;
        const float* wr = fw2 + tid * C4;
        #pragma unroll 8
        for (int k = 0; k < C4; k++) a += wr[k] * sfh[k];
        sfeat[tid] = a + fb2[tid];
    } else if (tid < OUTC + DBINS) {
        int d = tid - OUTC;
        float a = 0.f;
        const float* wr = dw + d * C4;
        #pragma unroll 8
        for (int k = 0; k < C4; k++) a += wr[k] * sx4[k];
        sdl[d] = a + db[d];
    } else if (tid == OUTC + DBINS) {
        float a = 0.f;
        #pragma unroll 8
        for (int k = 0; k < C4; k++) a += oww[k] * sx4[k];
        sprm[0] = 1.f / (1.f + expf(-(a + ob[0])));
    }
    __syncthreads();

    if (tid == 0) {
        float m = -1e30f;
        #pragma unroll
        for (int d = 0; d < DBINS; d++) m = fmaxf(m, sdl[d]);
        float sum = 0.f, zz = 0.f;
        #pragma unroll
        for (int d = 0; d < DBINS; d++) {
            float e = expf(sdl[d] - m);
            sum += e;
            zz  += e * (1.f + (float)d * (59.f / 15.f));
        }
        float z = zz / sum;

        float ihf = (float)imgh[0];
        float iwf = (float)imgw[0];
        float ys = ((float)h + 0.5f) * (ihf / (float)HF);
        float xs = ((float)w + 0.5f) * (iwf / (float)WF);

        const float* K = camK + b * 9;
        float fx = fmaxf(K[0], 1e-6f), fy = fmaxf(K[4], 1e-6f);
        float cx = K[2], cy = K[5];
        float xc = (xs - cx) * z / fx;
        float yc = (ys - cy) * z / fy;

        const float* T = Tlc + b * 16;
        float lx = T[0] * xc + T[1] * yc + T[2]  * z + T[3];
        float ly = T[4] * xc + T[5] * yc + T[6]  * z + T[7];
        float lz = T[8] * xc + T[9] * yc + T[10] * z + T[11];

        int xi = (int)floorf((lx + 51.2f) * 2.5f);
        int yi = (int)floorf((ly + 51.2f) * 2.5f);
        bool inb = (xi >= 0) && (xi < NXV) && (yi >= 0) && (yi < NYV) &&
                   (lz >= -5.f) && (lz < 3.f);
        float op = sprm[0];
        float bw = (op >= 0.05f && inb) ? op : 0.f;
        sprm[1] = bw;
        sprm[2] = __int_as_float(xi);
        sprm[3] = __int_as_float(yi);
    }
    __syncthreads();

    float bw = sprm[1];
    if (bw <= 0.f) return;
    int xi = __float_as_int(sprm[2]);
    int yi = __float_as_int(sprm[3]);

    #pragma unroll
    for (int tap = 0; tap < 9; tap++) {
        int dy = tap / 3 - 1;
        int dx = tap % 3 - 1;
        int ty = yi + dy;
        int tx = xi + dx;
        if ((unsigned)tx >= (unsigned)NXV || (unsigned)ty >= (unsigned)NYV) continue;
        float kwv = expf(-(float)(dx * dx + dy * dy) * (1.f / 1.28f));
        float sw = bw * kwv;
        int vox = b * SV + ty * NXV + tx;
        if (tid < OUTC) atomicAdd(&g_canvas[(size_t)vox * OUTC + tid], sfeat[tid] * sw);
        if (tid == OUTC) atomicAdd(&g_wacc[vox], sw);
    }
}

// ---------------- normalize + transpose (pix, C) -> (B, C, NY, NX) ----------------
__global__ void finalize_kernel(float* __restrict__ out)
{
    __shared__ float tile[OUTC][33];
    int gp  = blockIdx.x * 32;
    int tid = threadIdx.x;

    for (int i = tid; i < 32 * OUTC; i += 256) {
        int p = i >> 6;
        int c = i & 63;
        float wv  = g_wacc[gp + p];
        float inv = (wv > 0.f) ? (1.f / fmaxf(wv, 1e-6f)) : 0.f;
        tile[c][p] = g_canvas[(size_t)(gp + p) * OUTC + c] * inv;
    }
    __syncthreads();

    int b  = gp >> 16;
    int p0 = gp & 65535;
    for (int i = tid; i < OUTC * 32; i += 256) {
        int c = i >> 5;
        int x = i & 31;
        out[(((b * OUTC) + c) << 16) + p0 + x] = tile[c][x];
    }
}

// ---------------- launch ----------------
extern "C" void kernel_launch(void* const* d_in, const int* in_sizes, int n_in,
                              void* d_out, int out_size)
{
    const float* images = (const float*)d_in[0];
    const float* camK   = (const float*)d_in[1];
    const float* Tlc    = (const float*)d_in[2];
    const float* w1 = (const float*)d_in[3];
    const float* s1 = (const float*)d_in[4];
    const float* b1 = (const float*)d_in[5];
    const float* w2 = (const float*)d_in[6];
    const float* s2 = (const float*)d_in[7];
    const float* b2 = (const float*)d_in[8];
    const float* w3 = (const float*)d_in[9];
    const float* s3 = (const float*)d_in[10];
    const float* b3 = (const float*)d_in[11];
    const float* w4 = (const float*)d_in[12];
    const float* s4 = (const float*)d_in[13];
    const float* b4 = (const float*)d_in[14];
    const float* fw1 = (const float*)d_in[15];
    const float* fs1 = (const float*)d_in[16];
    const float* fb1 = (const float*)d_in[17];
    const float* fw2 = (const float*)d_in[18];
    const float* fb2 = (const float*)d_in[19];
    const float* dw  = (const float*)d_in[20];
    const float* db  = (const float*)d_in[21];
    const float* ow  = (const float*)d_in[22];
    const float* ob  = (const float*)d_in[23];
    const int* imgh  = (const int*)d_in[24];
    const int* imgw  = (const int*)d_in[25];
    float* out = (float*)d_out;

    float* x1;  cudaGetSymbolAddress((void**)&x1,  g_x1);
    float* x2;  cudaGetSymbolAddress((void**)&x2,  g_x2);
    float* x3;  cudaGetSymbolAddress((void**)&x3,  g_x3);
    float* x4;  cudaGetSymbolAddress((void**)&x4,  g_x4);
    float* fhp; cudaGetSymbolAddress((void**)&fhp, g_fh);
    float* wb2; cudaGetSymbolAddress((void**)&wb2, g_wb2);
    float* wb3; cudaGetSymbolAddress((void**)&wb3, g_wb3);
    float* wb4; cudaGetSymbolAddress((void**)&wb4, g_wb4);
    float* wb5; cudaGetSymbolAddress((void**)&wb5, g_wb5);

    cudaFuncSetAttribute((const void*)conv_gemm2<C1, C2, 2, H1, W1, H2, W2>,
                         cudaFuncAttributeMaxDynamicSharedMemorySize, SMEMB);
    cudaFuncSetAttribute((const void*)conv_gemm2<C2, C3, 2, H2, W2, H3, W3>,
                         cudaFuncAttributeMaxDynamicSharedMemorySize, SMEMB);
    cudaFuncSetAttribute((const void*)conv_gemm2<C3, C4, 2, H3, W3, HF, WF>,
                         cudaFuncAttributeMaxDynamicSharedMemorySize, SMEMB);
    cudaFuncSetAttribute((const void*)conv_gemm2<C4, C4, 1, HF, WF, HF, WF>,
                         cudaFuncAttributeMaxDynamicSharedMemorySize, SMEMB);

    wprep1<<<(36 * 32 + 255) / 256, 256>>>(w1);
    wprep_mma<<<(9  * 64  * 32 + 255) / 256, 256>>>(w2,  wb2, 32, 64, 9);
    wprep_mma<<<(18 * 128 * 32 + 255) / 256, 256>>>(w3,  wb3, 64, 128, 18);
    wprep_mma<<<(36 * 128 * 32 + 255) / 256, 256>>>(w4,  wb4, 128, 128, 36);
    wprep_mma<<<(36 * 128 * 32 + 255) / 256, 256>>>(fw1, wb5, 128, 128, 36);

    im2nhwc<<<(B_ * IMG_H * IMG_W + 255) / 256, 256>>>(images);
    zero_kernel<<<2048, 256>>>();

    conv1_kernel<<<B_ * H1 * W1 / 256, 256>>>(s1, b1);

    conv_gemm2<C1, C2, 2, H1, W1, H2, W2>
        <<<dim3(B_ * H2 * W2 / 128, 1), 256, SMEMB>>>(x1, wb2, s2, b2, x2);
    conv_gemm2<C2, C3, 2, H2, W2, H3, W3>
        <<<dim3(B_ * H3 * W3 / 128, 2), 256, SMEMB>>>(x2, wb3, s3, b3, x3);
    conv_gemm2<C3, C4, 2, H3, W3, HF, WF>
        <<<dim3(B_ * HF * WF / 128, 2), 256, SMEMB>>>(x3, wb4, s4, b4, x4);
    conv_gemm2<C4, C4, 1, HF, WF, HF, WF>
        <<<dim3(B_ * HF * WF / 128, 2), 256, SMEMB>>>(x4, wb5, fs1, fb1, fhp);

    heads_splat<<<B_ * HF * WF, 128>>>(x4, fhp, fw2, fb2, dw, db, ow, ob,
                                       camK, Tlc, imgh, imgw);

    finalize_kernel<<<B_ * SV / 32, 256>>>(out);
}